// round 13
// baseline (speedup 1.0000x reference)
#include <cuda_runtime.h>
#include <cuda_bf16.h>
#include <math.h>

#define N_NODES  50000
#define N_EDGES  1600000
#define EG       (N_EDGES / 4)
#define IN_CH    64
#define HID      16
#define NCLS     10
#define HID2P    16   // padded stride for layer-2 rows (64B-aligned; 12 used)

// ---------------- device scratch ----------------
__device__ __align__(16) float g_y1  [N_NODES * HID];    // x @ w_rel1
__device__ __align__(16) float g_agg1[N_NODES * HID];    // init x@w_root1+b1, += segsum(y1)
__device__ __align__(16) float g_y2  [N_NODES * HID2P];  // h @ w_rel2 (stride 16, 12 used)
__device__ __align__(16) float g_r2  [N_NODES * HID2P];  // h @ w_root2
__device__ __align__(16) float g_agg2[N_NODES * HID2P];  // segsum(y2)
__device__ int g_is64;                                   // edge dtype flag

// ---------------- kernels ----------------

// Fused layer-1 projections: y1 = x@w_rel1 -> g_y1 ; agg1 = x@w_root1 + b1.
// Also zeroes agg2 (used 12 floats per stride-16 row) and detects edge dtype.
// thread = pair*4 + part; pair = nodes {2p,2p+1};
// part 0/1 -> rel cols 0-7/8-15, part 2/3 -> root cols 0-7/8-15.
__global__ __launch_bounds__(256) void k_lin1(const float* __restrict__ x,
                                              const float* __restrict__ w_rel,
                                              const float* __restrict__ w_root,
                                              const float* __restrict__ b1,
                                              const int* __restrict__ ei32) {
    if (blockIdx.x == gridDim.x - 1) {
        __shared__ int s_or;
        if (threadIdx.x == 0) s_or = 0;
        __syncthreads();
        int v = 0;
        for (int i = threadIdx.x; i < 1024; i += 256)
            v |= ei32[2 * i + 1];
        if (v) atomicOr(&s_or, 1);
        __syncthreads();
        if (threadIdx.x == 0) g_is64 = (s_or == 0) ? 1 : 0;
        return;
    }

    __shared__ float sw[IN_CH * HID];   // 4 KB
    __shared__ float su[IN_CH * HID];   // 4 KB
    __shared__ float sb[HID];
    for (int i = threadIdx.x; i < IN_CH * HID; i += 256) {
        sw[i] = w_rel[i];
        su[i] = w_root[i];
    }
    if (threadIdx.x < HID) sb[threadIdx.x] = b1[threadIdx.x];
    __syncthreads();

    int t = blockIdx.x * 256 + threadIdx.x;
    int pair = t >> 2;
    if (pair >= N_NODES / 2) return;
    int part = t & 3;
    int n0 = pair * 2, n1 = n0 + 1;

    // Zero the used 3 float4s of each agg2 row (rows of 4 float4s, stride 16).
    {
        float4 z = make_float4(0.f, 0.f, 0.f, 0.f);
        float4* az = reinterpret_cast<float4*>(g_agg2 + (size_t)pair * 2 * HID2P);
        if (part == 0)      { az[0] = z; az[1] = z; }
        else if (part == 1) { az[2] = z; az[4] = z; }
        else if (part == 2) { az[5] = z; az[6] = z; }
        // part 3: none
    }

    const float* w = (part < 2) ? sw : su;
    int jbase = (part & 1) * 8;
    bool isRoot = (part >= 2);

    float a0[8], a1[8];
#pragma unroll
    for (int j = 0; j < 8; j++) {
        float init = isRoot ? sb[jbase + j] : 0.f;
        a0[j] = init; a1[j] = init;
    }

    const float4* x0 = reinterpret_cast<const float4*>(x + (size_t)n0 * IN_CH);
    const float4* x1 = reinterpret_cast<const float4*>(x + (size_t)n1 * IN_CH);
#pragma unroll
    for (int k4 = 0; k4 < IN_CH / 4; k4++) {
        float4 v0 = __ldg(x0 + k4);
        float4 v1 = __ldg(x1 + k4);
        float s0[4] = {v0.x, v0.y, v0.z, v0.w};
        float s1[4] = {v1.x, v1.y, v1.z, v1.w};
#pragma unroll
        for (int u = 0; u < 4; u++) {
            const float* wr = w + (k4 * 4 + u) * HID + jbase;
#pragma unroll
            for (int j = 0; j < 8; j++) {
                float wv = wr[j];
                a0[j] = fmaf(s0[u], wv, a0[j]);
                a1[j] = fmaf(s1[u], wv, a1[j]);
            }
        }
    }
    float* base = isRoot ? g_agg1 : g_y1;
    float* d0 = base + (size_t)n0 * HID + jbase;
    float* d1 = base + (size_t)n1 * HID + jbase;
    reinterpret_cast<float4*>(d0)[0] = make_float4(a0[0], a0[1], a0[2], a0[3]);
    reinterpret_cast<float4*>(d0)[1] = make_float4(a0[4], a0[5], a0[6], a0[7]);
    reinterpret_cast<float4*>(d1)[0] = make_float4(a1[0], a1[1], a1[2], a1[3]);
    reinterpret_cast<float4*>(d1)[1] = make_float4(a1[4], a1[5], a1[6], a1[7]);
}

// Layer-1 scatter, ILP=4: lanes q=0..3 share an edge group (coalesced rows).
__global__ __launch_bounds__(256) void k_scat1(const void* __restrict__ ei) {
    const bool is64 = (g_is64 != 0);
    int t = blockIdx.x * 256 + threadIdx.x;
    int eg = t >> 2;
    if (eg >= EG) return;
    int q = t & 3;
    int s[4], d[4];
    if (is64) {
        const long long* p = (const long long*)ei;
#pragma unroll
        for (int i = 0; i < 4; i++) {
            s[i] = (int)p[eg * 4 + i];
            d[i] = (int)p[N_EDGES + eg * 4 + i];
        }
    } else {
        const int* p = (const int*)ei;
        int4 sv = __ldg(reinterpret_cast<const int4*>(p) + eg);
        int4 dv = __ldg(reinterpret_cast<const int4*>(p + N_EDGES) + eg);
        s[0] = sv.x; s[1] = sv.y; s[2] = sv.z; s[3] = sv.w;
        d[0] = dv.x; d[1] = dv.y; d[2] = dv.z; d[3] = dv.w;
    }
    float4 v[4];
#pragma unroll
    for (int i = 0; i < 4; i++)
        v[i] = __ldg(reinterpret_cast<const float4*>(g_y1 + (size_t)s[i] * HID) + q);
#pragma unroll
    for (int i = 0; i < 4; i++) {
        float* dp = g_agg1 + (size_t)d[i] * HID + q * 4;
        asm volatile("red.global.add.v4.f32 [%0], {%1, %2, %3, %4};"
                     :: "l"(dp), "f"(v[i].x), "f"(v[i].y), "f"(v[i].z), "f"(v[i].w)
                     : "memory");
    }
}

// y2 = relu(agg1) @ w_rel2 (agg1 holds agg + root + bias). 4 threads/node,
// shfl_xor reduce over the 4-lane group, lane 0 stores stride-16 row.
__global__ __launch_bounds__(256) void k_lin2h(const float* __restrict__ w_rel2) {
    __shared__ float sw[HID * NCLS];
    for (int i = threadIdx.x; i < HID * NCLS; i += 256) sw[i] = w_rel2[i];
    __syncthreads();

    int t = blockIdx.x * 256 + threadIdx.x;
    int node = t >> 2;
    int sub = t & 3;
    bool valid = (node < N_NODES);

    float h[4] = {0.f, 0.f, 0.f, 0.f};
    if (valid) {
        float4 a = *(reinterpret_cast<const float4*>(g_agg1 + (size_t)node * HID) + sub);
        h[0] = a.x > 0.f ? a.x : 0.f;
        h[1] = a.y > 0.f ? a.y : 0.f;
        h[2] = a.z > 0.f ? a.z : 0.f;
        h[3] = a.w > 0.f ? a.w : 0.f;
    }
    float y[NCLS];
#pragma unroll
    for (int c = 0; c < NCLS; c++) y[c] = 0.f;
#pragma unroll
    for (int j = 0; j < 4; j++) {
        const float* wr = sw + (sub * 4 + j) * NCLS;
#pragma unroll
        for (int c = 0; c < NCLS; c++)
            y[c] = fmaf(h[j], wr[c], y[c]);
    }
#pragma unroll
    for (int c = 0; c < NCLS; c++) {
        y[c] += __shfl_xor_sync(0xffffffff, y[c], 1);
        y[c] += __shfl_xor_sync(0xffffffff, y[c], 2);
    }
    if (valid && sub == 0) {
        float4* y2 = reinterpret_cast<float4*>(g_y2 + (size_t)node * HID2P);
        y2[0] = make_float4(y[0], y[1], y[2], y[3]);
        y2[1] = make_float4(y[4], y[5], y[6], y[7]);
        y2[2] = make_float4(y[8], y[9], 0.f, 0.f);
    }
}

// r2 = relu(agg1) @ w_root2 — side stream, hidden under scat2.
__global__ __launch_bounds__(256) void k_lin2r(const float* __restrict__ w_root2) {
    __shared__ float su[HID * NCLS];
    for (int i = threadIdx.x; i < HID * NCLS; i += 256) su[i] = w_root2[i];
    __syncthreads();

    int t = blockIdx.x * 256 + threadIdx.x;
    int node = t >> 2;
    int sub = t & 3;
    bool valid = (node < N_NODES);

    float h[4] = {0.f, 0.f, 0.f, 0.f};
    if (valid) {
        float4 a = *(reinterpret_cast<const float4*>(g_agg1 + (size_t)node * HID) + sub);
        h[0] = a.x > 0.f ? a.x : 0.f;
        h[1] = a.y > 0.f ? a.y : 0.f;
        h[2] = a.z > 0.f ? a.z : 0.f;
        h[3] = a.w > 0.f ? a.w : 0.f;
    }
    float y[NCLS];
#pragma unroll
    for (int c = 0; c < NCLS; c++) y[c] = 0.f;
#pragma unroll
    for (int j = 0; j < 4; j++) {
        const float* wr = su + (sub * 4 + j) * NCLS;
#pragma unroll
        for (int c = 0; c < NCLS; c++)
            y[c] = fmaf(h[j], wr[c], y[c]);
    }
#pragma unroll
    for (int c = 0; c < NCLS; c++) {
        y[c] += __shfl_xor_sync(0xffffffff, y[c], 1);
        y[c] += __shfl_xor_sync(0xffffffff, y[c], 2);
    }
    if (valid && sub == 0) {
        float4* r2 = reinterpret_cast<float4*>(g_r2 + (size_t)node * HID2P);
        r2[0] = make_float4(y[0], y[1], y[2], y[3]);
        r2[1] = make_float4(y[4], y[5], y[6], y[7]);
        r2[2] = make_float4(y[8], y[9], 0.f, 0.f);
    }
}

// Layer-2 scatter, ILP=4, stride-16 rows (64B-aligned; no line crossing).
__global__ __launch_bounds__(256) void k_scat2(const void* __restrict__ ei) {
    const bool is64 = (g_is64 != 0);
    unsigned t = blockIdx.x * 256 + threadIdx.x;
    if (t >= 3u * EG) return;
    unsigned eg = (unsigned)(((unsigned long long)t * 0x55555556ULL) >> 32);  // t/3
    unsigned q = t - eg * 3u;
    int s[4], d[4];
    if (is64) {
        const long long* p = (const long long*)ei;
#pragma unroll
        for (int i = 0; i < 4; i++) {
            s[i] = (int)p[eg * 4 + i];
            d[i] = (int)p[N_EDGES + eg * 4 + i];
        }
    } else {
        const int* p = (const int*)ei;
        int4 sv = __ldg(reinterpret_cast<const int4*>(p) + eg);
        int4 dv = __ldg(reinterpret_cast<const int4*>(p + N_EDGES) + eg);
        s[0] = sv.x; s[1] = sv.y; s[2] = sv.z; s[3] = sv.w;
        d[0] = dv.x; d[1] = dv.y; d[2] = dv.z; d[3] = dv.w;
    }
    float4 v[4];
#pragma unroll
    for (int i = 0; i < 4; i++)
        v[i] = __ldg(reinterpret_cast<const float4*>(g_y2 + (size_t)s[i] * HID2P) + q);
#pragma unroll
    for (int i = 0; i < 4; i++) {
        float* dp = g_agg2 + (size_t)d[i] * HID2P + q * 4;
        asm volatile("red.global.add.v4.f32 [%0], {%1, %2, %3, %4};"
                     :: "l"(dp), "f"(v[i].x), "f"(v[i].y), "f"(v[i].z), "f"(v[i].w)
                     : "memory");
    }
}

// out = log_softmax(agg2 + b2 + r2), stride-16 rows in, stride-10 out.
__global__ __launch_bounds__(128) void k_out(const float* __restrict__ b2,
                                             float* __restrict__ out) {
    __shared__ float sb[NCLS];
    if (threadIdx.x < NCLS) sb[threadIdx.x] = b2[threadIdx.x];
    __syncthreads();

    int node = blockIdx.x * 128 + threadIdx.x;
    if (node >= N_NODES) return;

    float o[NCLS];
#pragma unroll
    for (int c = 0; c < NCLS; c++)
        o[c] = g_agg2[(size_t)node * HID2P + c] + sb[c] + g_r2[(size_t)node * HID2P + c];

    float m = o[0];
#pragma unroll
    for (int c = 1; c < NCLS; c++) m = fmaxf(m, o[c]);
    float sum = 0.f;
#pragma unroll
    for (int c = 0; c < NCLS; c++) sum += __expf(o[c] - m);
    float ls = m + logf(sum);
#pragma unroll
    for (int c = 0; c < NCLS; c++)
        out[(size_t)node * NCLS + c] = o[c] - ls;
}

// ---------------- launch ----------------
extern "C" void kernel_launch(void* const* d_in, const int* in_sizes, int n_in,
                              void* d_out, int out_size) {
    const float* x       = (const float*)d_in[0];
    const void*  ei      = d_in[1];
    const float* w_rel1  = (const float*)d_in[2];
    const float* b_rel1  = (const float*)d_in[3];
    const float* w_root1 = (const float*)d_in[4];
    const float* w_rel2  = (const float*)d_in[5];
    const float* b_rel2  = (const float*)d_in[6];
    const float* w_root2 = (const float*)d_in[7];
    float* out = (float*)d_out;

    static cudaStream_t s2 = nullptr;
    static cudaEvent_t evS1, evR2;
    if (!s2) {
        cudaStreamCreateWithFlags(&s2, cudaStreamNonBlocking);
        cudaEventCreateWithFlags(&evS1, cudaEventDisableTiming);
        cudaEventCreateWithFlags(&evR2, cudaEventDisableTiming);
    }

    const int lin1Blocks = (N_NODES / 2 * 4 + 255) / 256;      // 391
    const int lin2Blocks = (N_NODES * 4 + 255) / 256;          // 782
    const int nodeBlocks = (N_NODES + 127) / 128;
    const int scat1Blocks = (EG * 4 + 255) / 256;
    const int scat2Blocks = ((int)(3u * EG) + 255) / 256;

    // Main stream: lin1 -> scat1 -> lin2h -> scat2 -> out.
    k_lin1<<<lin1Blocks + 1, 256>>>(x, w_rel1, w_root1, b_rel1, (const int*)ei);
    k_scat1<<<scat1Blocks, 256>>>(ei);
    cudaEventRecord(evS1, 0);

    k_lin2h<<<lin2Blocks, 256>>>(w_rel2);

    // Side stream: lin2r after scat1, hidden under lin2h + scat2.
    cudaStreamWaitEvent(s2, evS1, 0);
    k_lin2r<<<lin2Blocks, 256, 0, s2>>>(w_root2);
    cudaEventRecord(evR2, s2);

    k_scat2<<<scat2Blocks, 256>>>(ei);

    cudaStreamWaitEvent(0, evR2, 0);
    k_out<<<nodeBlocks, 128>>>(b_rel2, out);
}

// round 14
// speedup vs baseline: 1.0785x; 1.0785x over previous
#include <cuda_runtime.h>
#include <cuda_bf16.h>
#include <math.h>

#define N_NODES  50000
#define N_EDGES  1600000
#define EG       (N_EDGES / 4)
#define IN_CH    64
#define HID      16
#define NCLS     10
#define HID2P    12

// ---------------- device scratch ----------------
__device__ __align__(16) float g_y1  [N_NODES * HID];    // x @ w_rel1
__device__ __align__(16) float g_agg1[N_NODES * HID];    // 0 + RED(root+b1) + RED(edges)
__device__ __align__(16) float g_y2  [N_NODES * HID2P];  // h @ w_rel2 (padded)
__device__ __align__(16) float g_r2  [N_NODES * HID2P];  // h @ w_root2
__device__ __align__(16) float g_agg2[N_NODES * HID2P];  // segsum(y2)
__device__ int g_is64;                                   // edge dtype flag

// ---------------- kernels ----------------

// y1 = x @ w_rel1; zero agg1; detect edge dtype (last block).
// thread = pair*4 + part; pair = nodes {2p,2p+1}; part = column quarter.
__global__ __launch_bounds__(256) void k_lin1y(const float* __restrict__ x,
                                               const float* __restrict__ w_rel,
                                               const int* __restrict__ ei32) {
    if (blockIdx.x == gridDim.x - 1) {
        __shared__ int s_or;
        if (threadIdx.x == 0) s_or = 0;
        __syncthreads();
        int v = 0;
        for (int i = threadIdx.x; i < 1024; i += 256)
            v |= ei32[2 * i + 1];
        if (v) atomicOr(&s_or, 1);
        __syncthreads();
        if (threadIdx.x == 0) g_is64 = (s_or == 0) ? 1 : 0;
        return;
    }

    __shared__ float sw[IN_CH * HID];
    for (int i = threadIdx.x; i < IN_CH * HID; i += 256) sw[i] = w_rel[i];
    __syncthreads();

    int t = blockIdx.x * 256 + threadIdx.x;
    int pair = t >> 2;
    if (pair >= N_NODES / 2) return;
    int part = t & 3;
    int jbase = part * 4;
    int n0 = pair * 2, n1 = n0 + 1;

    // Zero agg1 for this pair: 8 float4s, 2 per part.
    {
        float4 z = make_float4(0.f, 0.f, 0.f, 0.f);
        float4* az = reinterpret_cast<float4*>(g_agg1 + (size_t)pair * 2 * HID);
        az[2 * part] = z;
        az[2 * part + 1] = z;
    }

    float a0[4] = {0.f, 0.f, 0.f, 0.f};
    float a1[4] = {0.f, 0.f, 0.f, 0.f};
    const float4* x0 = reinterpret_cast<const float4*>(x + (size_t)n0 * IN_CH);
    const float4* x1 = reinterpret_cast<const float4*>(x + (size_t)n1 * IN_CH);
#pragma unroll
    for (int k4 = 0; k4 < IN_CH / 4; k4++) {
        float4 v0 = __ldg(x0 + k4);
        float4 v1 = __ldg(x1 + k4);
        float s0[4] = {v0.x, v0.y, v0.z, v0.w};
        float s1[4] = {v1.x, v1.y, v1.z, v1.w};
#pragma unroll
        for (int u = 0; u < 4; u++) {
            const float* wr = sw + (k4 * 4 + u) * HID + jbase;
#pragma unroll
            for (int j = 0; j < 4; j++) {
                float wv = wr[j];
                a0[j] = fmaf(s0[u], wv, a0[j]);
                a1[j] = fmaf(s1[u], wv, a1[j]);
            }
        }
    }
    *reinterpret_cast<float4*>(g_y1 + (size_t)n0 * HID + jbase) =
        make_float4(a0[0], a0[1], a0[2], a0[3]);
    *reinterpret_cast<float4*>(g_y1 + (size_t)n1 * HID + jbase) =
        make_float4(a1[0], a1[1], a1[2], a1[3]);
}

// Root fold: RED-add (x@w_root1 + b1) into agg1. Commutes with scat1's REDs,
// so it runs on the side stream CONCURRENTLY with scat1 (after lin1y's zero).
// Also zeroes agg2.
__global__ __launch_bounds__(256) void k_lin1r(const float* __restrict__ x,
                                               const float* __restrict__ w_root,
                                               const float* __restrict__ b1) {
    __shared__ float su[IN_CH * HID];
    __shared__ float sb[HID];
    for (int i = threadIdx.x; i < IN_CH * HID; i += 256) su[i] = w_root[i];
    if (threadIdx.x < HID) sb[threadIdx.x] = b1[threadIdx.x];
    __syncthreads();

    int t = blockIdx.x * 256 + threadIdx.x;
    int pair = t >> 2;
    if (pair >= N_NODES / 2) return;
    int part = t & 3;
    int jbase = part * 4;
    int n0 = pair * 2, n1 = n0 + 1;

    // Zero agg2 for this pair: 6 float4s over 4 parts.
    {
        float4 z = make_float4(0.f, 0.f, 0.f, 0.f);
        float4* az = reinterpret_cast<float4*>(g_agg2 + (size_t)pair * 2 * HID2P);
        if (part == 0)      { az[0] = z; az[1] = z; }
        else if (part == 1) { az[2] = z; az[3] = z; }
        else if (part == 2) { az[4] = z; }
        else                { az[5] = z; }
    }

    float a0[4], a1[4];
#pragma unroll
    for (int j = 0; j < 4; j++) { a0[j] = sb[jbase + j]; a1[j] = sb[jbase + j]; }
    const float4* x0 = reinterpret_cast<const float4*>(x + (size_t)n0 * IN_CH);
    const float4* x1 = reinterpret_cast<const float4*>(x + (size_t)n1 * IN_CH);
#pragma unroll
    for (int k4 = 0; k4 < IN_CH / 4; k4++) {
        float4 v0 = __ldg(x0 + k4);
        float4 v1 = __ldg(x1 + k4);
        float s0[4] = {v0.x, v0.y, v0.z, v0.w};
        float s1[4] = {v1.x, v1.y, v1.z, v1.w};
#pragma unroll
        for (int u = 0; u < 4; u++) {
            const float* wr = su + (k4 * 4 + u) * HID + jbase;
#pragma unroll
            for (int j = 0; j < 4; j++) {
                float wv = wr[j];
                a0[j] = fmaf(s0[u], wv, a0[j]);
                a1[j] = fmaf(s1[u], wv, a1[j]);
            }
        }
    }
    float* p0 = g_agg1 + (size_t)n0 * HID + jbase;
    float* p1 = g_agg1 + (size_t)n1 * HID + jbase;
    asm volatile("red.global.add.v4.f32 [%0], {%1, %2, %3, %4};"
                 :: "l"(p0), "f"(a0[0]), "f"(a0[1]), "f"(a0[2]), "f"(a0[3]) : "memory");
    asm volatile("red.global.add.v4.f32 [%0], {%1, %2, %3, %4};"
                 :: "l"(p1), "f"(a1[0]), "f"(a1[1]), "f"(a1[2]), "f"(a1[3]) : "memory");
}

// Layer-1 scatter, ILP=4: lanes q=0..3 share an edge group (coalesced rows).
__global__ __launch_bounds__(256) void k_scat1(const void* __restrict__ ei) {
    const bool is64 = (g_is64 != 0);
    int t = blockIdx.x * 256 + threadIdx.x;
    int eg = t >> 2;
    if (eg >= EG) return;
    int q = t & 3;
    int s[4], d[4];
    if (is64) {
        const long long* p = (const long long*)ei;
#pragma unroll
        for (int i = 0; i < 4; i++) {
            s[i] = (int)p[eg * 4 + i];
            d[i] = (int)p[N_EDGES + eg * 4 + i];
        }
    } else {
        const int* p = (const int*)ei;
        int4 sv = __ldg(reinterpret_cast<const int4*>(p) + eg);
        int4 dv = __ldg(reinterpret_cast<const int4*>(p + N_EDGES) + eg);
        s[0] = sv.x; s[1] = sv.y; s[2] = sv.z; s[3] = sv.w;
        d[0] = dv.x; d[1] = dv.y; d[2] = dv.z; d[3] = dv.w;
    }
    float4 v[4];
#pragma unroll
    for (int i = 0; i < 4; i++)
        v[i] = __ldg(reinterpret_cast<const float4*>(g_y1 + (size_t)s[i] * HID) + q);
#pragma unroll
    for (int i = 0; i < 4; i++) {
        float* dp = g_agg1 + (size_t)d[i] * HID + q * 4;
        asm volatile("red.global.add.v4.f32 [%0], {%1, %2, %3, %4};"
                     :: "l"(dp), "f"(v[i].x), "f"(v[i].y), "f"(v[i].z), "f"(v[i].w)
                     : "memory");
    }
}

// y2 = relu(agg1) @ w_rel2 (agg1 already holds agg + root + bias).
// 4 threads/node, shfl_xor reduce, lane 0 stores.
__global__ __launch_bounds__(256) void k_lin2h(const float* __restrict__ w_rel2) {
    __shared__ float sw[HID * NCLS];
    for (int i = threadIdx.x; i < HID * NCLS; i += 256) sw[i] = w_rel2[i];
    __syncthreads();

    int t = blockIdx.x * 256 + threadIdx.x;
    int node = t >> 2;
    int sub = t & 3;
    bool valid = (node < N_NODES);

    float h[4] = {0.f, 0.f, 0.f, 0.f};
    if (valid) {
        float4 a = *(reinterpret_cast<const float4*>(g_agg1 + (size_t)node * HID) + sub);
        h[0] = a.x > 0.f ? a.x : 0.f;
        h[1] = a.y > 0.f ? a.y : 0.f;
        h[2] = a.z > 0.f ? a.z : 0.f;
        h[3] = a.w > 0.f ? a.w : 0.f;
    }
    float y[NCLS];
#pragma unroll
    for (int c = 0; c < NCLS; c++) y[c] = 0.f;
#pragma unroll
    for (int j = 0; j < 4; j++) {
        const float* wr = sw + (sub * 4 + j) * NCLS;
#pragma unroll
        for (int c = 0; c < NCLS; c++)
            y[c] = fmaf(h[j], wr[c], y[c]);
    }
#pragma unroll
    for (int c = 0; c < NCLS; c++) {
        y[c] += __shfl_xor_sync(0xffffffff, y[c], 1);
        y[c] += __shfl_xor_sync(0xffffffff, y[c], 2);
    }
    if (valid && sub == 0) {
        float4* y2 = reinterpret_cast<float4*>(g_y2 + (size_t)node * HID2P);
        y2[0] = make_float4(y[0], y[1], y[2], y[3]);
        y2[1] = make_float4(y[4], y[5], y[6], y[7]);
        y2[2] = make_float4(y[8], y[9], 0.f, 0.f);
    }
}

// r2 = relu(agg1) @ w_root2 — side stream, hidden under scat2.
__global__ __launch_bounds__(256) void k_lin2r(const float* __restrict__ w_root2) {
    __shared__ float su[HID * NCLS];
    for (int i = threadIdx.x; i < HID * NCLS; i += 256) su[i] = w_root2[i];
    __syncthreads();

    int t = blockIdx.x * 256 + threadIdx.x;
    int node = t >> 2;
    int sub = t & 3;
    bool valid = (node < N_NODES);

    float h[4] = {0.f, 0.f, 0.f, 0.f};
    if (valid) {
        float4 a = *(reinterpret_cast<const float4*>(g_agg1 + (size_t)node * HID) + sub);
        h[0] = a.x > 0.f ? a.x : 0.f;
        h[1] = a.y > 0.f ? a.y : 0.f;
        h[2] = a.z > 0.f ? a.z : 0.f;
        h[3] = a.w > 0.f ? a.w : 0.f;
    }
    float y[NCLS];
#pragma unroll
    for (int c = 0; c < NCLS; c++) y[c] = 0.f;
#pragma unroll
    for (int j = 0; j < 4; j++) {
        const float* wr = su + (sub * 4 + j) * NCLS;
#pragma unroll
        for (int c = 0; c < NCLS; c++)
            y[c] = fmaf(h[j], wr[c], y[c]);
    }
#pragma unroll
    for (int c = 0; c < NCLS; c++) {
        y[c] += __shfl_xor_sync(0xffffffff, y[c], 1);
        y[c] += __shfl_xor_sync(0xffffffff, y[c], 2);
    }
    if (valid && sub == 0) {
        float4* r2 = reinterpret_cast<float4*>(g_r2 + (size_t)node * HID2P);
        r2[0] = make_float4(y[0], y[1], y[2], y[3]);
        r2[1] = make_float4(y[4], y[5], y[6], y[7]);
        r2[2] = make_float4(y[8], y[9], 0.f, 0.f);
    }
}

// Layer-2 scatter, ILP=4.
__global__ __launch_bounds__(256) void k_scat2(const void* __restrict__ ei) {
    const bool is64 = (g_is64 != 0);
    unsigned t = blockIdx.x * 256 + threadIdx.x;
    if (t >= 3u * EG) return;
    unsigned eg = (unsigned)(((unsigned long long)t * 0x55555556ULL) >> 32);  // t/3
    unsigned q = t - eg * 3u;
    int s[4], d[4];
    if (is64) {
        const long long* p = (const long long*)ei;
#pragma unroll
        for (int i = 0; i < 4; i++) {
            s[i] = (int)p[eg * 4 + i];
            d[i] = (int)p[N_EDGES + eg * 4 + i];
        }
    } else {
        const int* p = (const int*)ei;
        int4 sv = __ldg(reinterpret_cast<const int4*>(p) + eg);
        int4 dv = __ldg(reinterpret_cast<const int4*>(p + N_EDGES) + eg);
        s[0] = sv.x; s[1] = sv.y; s[2] = sv.z; s[3] = sv.w;
        d[0] = dv.x; d[1] = dv.y; d[2] = dv.z; d[3] = dv.w;
    }
    float4 v[4];
#pragma unroll
    for (int i = 0; i < 4; i++)
        v[i] = __ldg(reinterpret_cast<const float4*>(g_y2 + (size_t)s[i] * HID2P) + q);
#pragma unroll
    for (int i = 0; i < 4; i++) {
        float* dp = g_agg2 + (size_t)d[i] * HID2P + q * 4;
        asm volatile("red.global.add.v4.f32 [%0], {%1, %2, %3, %4};"
                     :: "l"(dp), "f"(v[i].x), "f"(v[i].y), "f"(v[i].z), "f"(v[i].w)
                     : "memory");
    }
}

// out = log_softmax(agg2 + b2 + r2)
__global__ __launch_bounds__(128) void k_out(const float* __restrict__ b2,
                                             float* __restrict__ out) {
    __shared__ float sb[NCLS];
    if (threadIdx.x < NCLS) sb[threadIdx.x] = b2[threadIdx.x];
    __syncthreads();

    int node = blockIdx.x * 128 + threadIdx.x;
    if (node >= N_NODES) return;

    float o[NCLS];
#pragma unroll
    for (int c = 0; c < NCLS; c++)
        o[c] = g_agg2[(size_t)node * HID2P + c] + sb[c] + g_r2[(size_t)node * HID2P + c];

    float m = o[0];
#pragma unroll
    for (int c = 1; c < NCLS; c++) m = fmaxf(m, o[c]);
    float sum = 0.f;
#pragma unroll
    for (int c = 0; c < NCLS; c++) sum += __expf(o[c] - m);
    float ls = m + logf(sum);
#pragma unroll
    for (int c = 0; c < NCLS; c++)
        out[(size_t)node * NCLS + c] = o[c] - ls;
}

// ---------------- launch ----------------
extern "C" void kernel_launch(void* const* d_in, const int* in_sizes, int n_in,
                              void* d_out, int out_size) {
    const float* x       = (const float*)d_in[0];
    const void*  ei      = d_in[1];
    const float* w_rel1  = (const float*)d_in[2];
    const float* b_rel1  = (const float*)d_in[3];
    const float* w_root1 = (const float*)d_in[4];
    const float* w_rel2  = (const float*)d_in[5];
    const float* b_rel2  = (const float*)d_in[6];
    const float* w_root2 = (const float*)d_in[7];
    float* out = (float*)d_out;

    static cudaStream_t s2 = nullptr;
    static cudaEvent_t evY, evR1, evS1, evR2;
    if (!s2) {
        cudaStreamCreateWithFlags(&s2, cudaStreamNonBlocking);
        cudaEventCreateWithFlags(&evY,  cudaEventDisableTiming);
        cudaEventCreateWithFlags(&evR1, cudaEventDisableTiming);
        cudaEventCreateWithFlags(&evS1, cudaEventDisableTiming);
        cudaEventCreateWithFlags(&evR2, cudaEventDisableTiming);
    }

    const int lin1Blocks = (N_NODES / 2 * 4 + 255) / 256;      // 391
    const int lin2Blocks = (N_NODES * 4 + 255) / 256;          // 782
    const int nodeBlocks = (N_NODES + 127) / 128;
    const int scat1Blocks = (EG * 4 + 255) / 256;
    const int scat2Blocks = ((int)(3u * EG) + 255) / 256;

    // Main: lin1y -> scat1 -> (wait lin1r) lin2h -> scat2 -> (wait lin2r) out
    // Side: (wait lin1y) lin1r [REDs race with scat1] -> (wait scat1) lin2r
    k_lin1y<<<lin1Blocks + 1, 256>>>(x, w_rel1, (const int*)ei);   // +1 detect
    cudaEventRecord(evY, 0);
    cudaStreamWaitEvent(s2, evY, 0);           // agg1 zeroed before root REDs
    k_lin1r<<<lin1Blocks, 256, 0, s2>>>(x, w_root1, b_rel1);
    cudaEventRecord(evR1, s2);

    k_scat1<<<scat1Blocks, 256>>>(ei);         // concurrent with lin1r
    cudaEventRecord(evS1, 0);

    cudaStreamWaitEvent(0, evR1, 0);           // agg1 fully assembled
    k_lin2h<<<lin2Blocks, 256>>>(w_rel2);

    cudaStreamWaitEvent(s2, evS1, 0);
    k_lin2r<<<lin2Blocks, 256, 0, s2>>>(w_root2);
    cudaEventRecord(evR2, s2);

    k_scat2<<<scat2Blocks, 256>>>(ei);

    cudaStreamWaitEvent(0, evR2, 0);
    k_out<<<nodeBlocks, 128>>>(b_rel2, out);
}

// round 15
// speedup vs baseline: 1.0789x; 1.0004x over previous
#include <cuda_runtime.h>
#include <cuda_bf16.h>
#include <math.h>

#define N_NODES  50000
#define N_EDGES  1600000
#define EG       (N_EDGES / 4)
#define IN_CH    64
#define HID      16
#define NCLS     10
#define HID2P    12

// ---------------- device scratch ----------------
__device__ __align__(16) float g_y1  [N_NODES * HID];    // x @ w_rel1
__device__ __align__(16) float g_agg1[N_NODES * HID];    // 0 + RED(root1+b1) + RED(edges)
__device__ __align__(16) float g_y2  [N_NODES * HID2P];  // h @ w_rel2 (padded)
__device__ __align__(16) float g_agg2[N_NODES * HID2P];  // 0 + RED(root2+b2) + RED(edges)
__device__ int g_is64;                                   // edge dtype flag

// ---------------- kernels ----------------

// y1 = x @ w_rel1; zero agg1; detect edge dtype (last block).
// thread = pair*4 + part; pair = nodes {2p,2p+1}; part = column quarter.
__global__ __launch_bounds__(256) void k_lin1y(const float* __restrict__ x,
                                               const float* __restrict__ w_rel,
                                               const int* __restrict__ ei32) {
    if (blockIdx.x == gridDim.x - 1) {
        __shared__ int s_or;
        if (threadIdx.x == 0) s_or = 0;
        __syncthreads();
        int v = 0;
        for (int i = threadIdx.x; i < 1024; i += 256)
            v |= ei32[2 * i + 1];
        if (v) atomicOr(&s_or, 1);
        __syncthreads();
        if (threadIdx.x == 0) g_is64 = (s_or == 0) ? 1 : 0;
        return;
    }

    __shared__ float sw[IN_CH * HID];
    for (int i = threadIdx.x; i < IN_CH * HID; i += 256) sw[i] = w_rel[i];
    __syncthreads();

    int t = blockIdx.x * 256 + threadIdx.x;
    int pair = t >> 2;
    if (pair >= N_NODES / 2) return;
    int part = t & 3;
    int jbase = part * 4;
    int n0 = pair * 2, n1 = n0 + 1;

    // Zero agg1 for this pair: 8 float4s, 2 per part.
    {
        float4 z = make_float4(0.f, 0.f, 0.f, 0.f);
        float4* az = reinterpret_cast<float4*>(g_agg1 + (size_t)pair * 2 * HID);
        az[2 * part] = z;
        az[2 * part + 1] = z;
    }

    float a0[4] = {0.f, 0.f, 0.f, 0.f};
    float a1[4] = {0.f, 0.f, 0.f, 0.f};
    const float4* x0 = reinterpret_cast<const float4*>(x + (size_t)n0 * IN_CH);
    const float4* x1 = reinterpret_cast<const float4*>(x + (size_t)n1 * IN_CH);
#pragma unroll
    for (int k4 = 0; k4 < IN_CH / 4; k4++) {
        float4 v0 = __ldg(x0 + k4);
        float4 v1 = __ldg(x1 + k4);
        float s0[4] = {v0.x, v0.y, v0.z, v0.w};
        float s1[4] = {v1.x, v1.y, v1.z, v1.w};
#pragma unroll
        for (int u = 0; u < 4; u++) {
            const float* wr = sw + (k4 * 4 + u) * HID + jbase;
#pragma unroll
            for (int j = 0; j < 4; j++) {
                float wv = wr[j];
                a0[j] = fmaf(s0[u], wv, a0[j]);
                a1[j] = fmaf(s1[u], wv, a1[j]);
            }
        }
    }
    *reinterpret_cast<float4*>(g_y1 + (size_t)n0 * HID + jbase) =
        make_float4(a0[0], a0[1], a0[2], a0[3]);
    *reinterpret_cast<float4*>(g_y1 + (size_t)n1 * HID + jbase) =
        make_float4(a1[0], a1[1], a1[2], a1[3]);
}

// Root fold 1: RED-add (x@w_root1 + b1) into agg1. Commutes with scat1's
// REDs -> runs on side stream concurrently with scat1. Also zeroes agg2.
__global__ __launch_bounds__(256) void k_lin1r(const float* __restrict__ x,
                                               const float* __restrict__ w_root,
                                               const float* __restrict__ b1) {
    __shared__ float su[IN_CH * HID];
    __shared__ float sb[HID];
    for (int i = threadIdx.x; i < IN_CH * HID; i += 256) su[i] = w_root[i];
    if (threadIdx.x < HID) sb[threadIdx.x] = b1[threadIdx.x];
    __syncthreads();

    int t = blockIdx.x * 256 + threadIdx.x;
    int pair = t >> 2;
    if (pair >= N_NODES / 2) return;
    int part = t & 3;
    int jbase = part * 4;
    int n0 = pair * 2, n1 = n0 + 1;

    // Zero agg2 for this pair: 6 float4s over 4 parts.
    {
        float4 z = make_float4(0.f, 0.f, 0.f, 0.f);
        float4* az = reinterpret_cast<float4*>(g_agg2 + (size_t)pair * 2 * HID2P);
        if (part == 0)      { az[0] = z; az[1] = z; }
        else if (part == 1) { az[2] = z; az[3] = z; }
        else if (part == 2) { az[4] = z; }
        else                { az[5] = z; }
    }

    float a0[4], a1[4];
#pragma unroll
    for (int j = 0; j < 4; j++) { a0[j] = sb[jbase + j]; a1[j] = sb[jbase + j]; }
    const float4* x0 = reinterpret_cast<const float4*>(x + (size_t)n0 * IN_CH);
    const float4* x1 = reinterpret_cast<const float4*>(x + (size_t)n1 * IN_CH);
#pragma unroll
    for (int k4 = 0; k4 < IN_CH / 4; k4++) {
        float4 v0 = __ldg(x0 + k4);
        float4 v1 = __ldg(x1 + k4);
        float s0[4] = {v0.x, v0.y, v0.z, v0.w};
        float s1[4] = {v1.x, v1.y, v1.z, v1.w};
#pragma unroll
        for (int u = 0; u < 4; u++) {
            const float* wr = su + (k4 * 4 + u) * HID + jbase;
#pragma unroll
            for (int j = 0; j < 4; j++) {
                float wv = wr[j];
                a0[j] = fmaf(s0[u], wv, a0[j]);
                a1[j] = fmaf(s1[u], wv, a1[j]);
            }
        }
    }
    float* p0 = g_agg1 + (size_t)n0 * HID + jbase;
    float* p1 = g_agg1 + (size_t)n1 * HID + jbase;
    asm volatile("red.global.add.v4.f32 [%0], {%1, %2, %3, %4};"
                 :: "l"(p0), "f"(a0[0]), "f"(a0[1]), "f"(a0[2]), "f"(a0[3]) : "memory");
    asm volatile("red.global.add.v4.f32 [%0], {%1, %2, %3, %4};"
                 :: "l"(p1), "f"(a1[0]), "f"(a1[1]), "f"(a1[2]), "f"(a1[3]) : "memory");
}

// Layer-1 scatter, ILP=4: lanes q=0..3 share an edge group (coalesced rows).
__global__ __launch_bounds__(256) void k_scat1(const void* __restrict__ ei) {
    const bool is64 = (g_is64 != 0);
    int t = blockIdx.x * 256 + threadIdx.x;
    int eg = t >> 2;
    if (eg >= EG) return;
    int q = t & 3;
    int s[4], d[4];
    if (is64) {
        const long long* p = (const long long*)ei;
#pragma unroll
        for (int i = 0; i < 4; i++) {
            s[i] = (int)p[eg * 4 + i];
            d[i] = (int)p[N_EDGES + eg * 4 + i];
        }
    } else {
        const int* p = (const int*)ei;
        int4 sv = __ldg(reinterpret_cast<const int4*>(p) + eg);
        int4 dv = __ldg(reinterpret_cast<const int4*>(p + N_EDGES) + eg);
        s[0] = sv.x; s[1] = sv.y; s[2] = sv.z; s[3] = sv.w;
        d[0] = dv.x; d[1] = dv.y; d[2] = dv.z; d[3] = dv.w;
    }
    float4 v[4];
#pragma unroll
    for (int i = 0; i < 4; i++)
        v[i] = __ldg(reinterpret_cast<const float4*>(g_y1 + (size_t)s[i] * HID) + q);
#pragma unroll
    for (int i = 0; i < 4; i++) {
        float* dp = g_agg1 + (size_t)d[i] * HID + q * 4;
        asm volatile("red.global.add.v4.f32 [%0], {%1, %2, %3, %4};"
                     :: "l"(dp), "f"(v[i].x), "f"(v[i].y), "f"(v[i].z), "f"(v[i].w)
                     : "memory");
    }
}

// y2 = relu(agg1) @ w_rel2 (agg1 already holds agg + root + bias).
// 4 threads/node, shfl_xor reduce, lane 0 stores.
__global__ __launch_bounds__(256) void k_lin2h(const float* __restrict__ w_rel2) {
    __shared__ float sw[HID * NCLS];
    for (int i = threadIdx.x; i < HID * NCLS; i += 256) sw[i] = w_rel2[i];
    __syncthreads();

    int t = blockIdx.x * 256 + threadIdx.x;
    int node = t >> 2;
    int sub = t & 3;
    bool valid = (node < N_NODES);

    float h[4] = {0.f, 0.f, 0.f, 0.f};
    if (valid) {
        float4 a = *(reinterpret_cast<const float4*>(g_agg1 + (size_t)node * HID) + sub);
        h[0] = a.x > 0.f ? a.x : 0.f;
        h[1] = a.y > 0.f ? a.y : 0.f;
        h[2] = a.z > 0.f ? a.z : 0.f;
        h[3] = a.w > 0.f ? a.w : 0.f;
    }
    float y[NCLS];
#pragma unroll
    for (int c = 0; c < NCLS; c++) y[c] = 0.f;
#pragma unroll
    for (int j = 0; j < 4; j++) {
        const float* wr = sw + (sub * 4 + j) * NCLS;
#pragma unroll
        for (int c = 0; c < NCLS; c++)
            y[c] = fmaf(h[j], wr[c], y[c]);
    }
#pragma unroll
    for (int c = 0; c < NCLS; c++) {
        y[c] += __shfl_xor_sync(0xffffffff, y[c], 1);
        y[c] += __shfl_xor_sync(0xffffffff, y[c], 2);
    }
    if (valid && sub == 0) {
        float4* y2 = reinterpret_cast<float4*>(g_y2 + (size_t)node * HID2P);
        y2[0] = make_float4(y[0], y[1], y[2], y[3]);
        y2[1] = make_float4(y[4], y[5], y[6], y[7]);
        y2[2] = make_float4(y[8], y[9], 0.f, 0.f);
    }
}

// Root fold 2: RED-add (relu(agg1)@w_root2 + b2) into agg2. Commutes with
// scat2's REDs -> side stream, concurrent with lin2h/scat2.
__global__ __launch_bounds__(256) void k_lin2r(const float* __restrict__ w_root2,
                                               const float* __restrict__ b2) {
    __shared__ float su[HID * NCLS];
    __shared__ float sb[NCLS];
    for (int i = threadIdx.x; i < HID * NCLS; i += 256) su[i] = w_root2[i];
    if (threadIdx.x < NCLS) sb[threadIdx.x] = b2[threadIdx.x];
    __syncthreads();

    int t = blockIdx.x * 256 + threadIdx.x;
    int node = t >> 2;
    int sub = t & 3;
    bool valid = (node < N_NODES);

    float h[4] = {0.f, 0.f, 0.f, 0.f};
    if (valid) {
        float4 a = *(reinterpret_cast<const float4*>(g_agg1 + (size_t)node * HID) + sub);
        h[0] = a.x > 0.f ? a.x : 0.f;
        h[1] = a.y > 0.f ? a.y : 0.f;
        h[2] = a.z > 0.f ? a.z : 0.f;
        h[3] = a.w > 0.f ? a.w : 0.f;
    }
    float y[NCLS];
#pragma unroll
    for (int c = 0; c < NCLS; c++) y[c] = (sub == 0) ? sb[c] : 0.f;  // b2 once
#pragma unroll
    for (int j = 0; j < 4; j++) {
        const float* wr = su + (sub * 4 + j) * NCLS;
#pragma unroll
        for (int c = 0; c < NCLS; c++)
            y[c] = fmaf(h[j], wr[c], y[c]);
    }
#pragma unroll
    for (int c = 0; c < NCLS; c++) {
        y[c] += __shfl_xor_sync(0xffffffff, y[c], 1);
        y[c] += __shfl_xor_sync(0xffffffff, y[c], 2);
    }
    if (valid && sub == 0) {
        float* p = g_agg2 + (size_t)node * HID2P;
        asm volatile("red.global.add.v4.f32 [%0], {%1, %2, %3, %4};"
                     :: "l"(p), "f"(y[0]), "f"(y[1]), "f"(y[2]), "f"(y[3]) : "memory");
        asm volatile("red.global.add.v4.f32 [%0], {%1, %2, %3, %4};"
                     :: "l"(p + 4), "f"(y[4]), "f"(y[5]), "f"(y[6]), "f"(y[7]) : "memory");
        asm volatile("red.global.add.v4.f32 [%0], {%1, %2, %3, %4};"
                     :: "l"(p + 8), "f"(y[8]), "f"(y[9]), "f"(0.f), "f"(0.f) : "memory");
    }
}

// Layer-2 scatter, ILP=4.
__global__ __launch_bounds__(256) void k_scat2(const void* __restrict__ ei) {
    const bool is64 = (g_is64 != 0);
    unsigned t = blockIdx.x * 256 + threadIdx.x;
    if (t >= 3u * EG) return;
    unsigned eg = (unsigned)(((unsigned long long)t * 0x55555556ULL) >> 32);  // t/3
    unsigned q = t - eg * 3u;
    int s[4], d[4];
    if (is64) {
        const long long* p = (const long long*)ei;
#pragma unroll
        for (int i = 0; i < 4; i++) {
            s[i] = (int)p[eg * 4 + i];
            d[i] = (int)p[N_EDGES + eg * 4 + i];
        }
    } else {
        const int* p = (const int*)ei;
        int4 sv = __ldg(reinterpret_cast<const int4*>(p) + eg);
        int4 dv = __ldg(reinterpret_cast<const int4*>(p + N_EDGES) + eg);
        s[0] = sv.x; s[1] = sv.y; s[2] = sv.z; s[3] = sv.w;
        d[0] = dv.x; d[1] = dv.y; d[2] = dv.z; d[3] = dv.w;
    }
    float4 v[4];
#pragma unroll
    for (int i = 0; i < 4; i++)
        v[i] = __ldg(reinterpret_cast<const float4*>(g_y2 + (size_t)s[i] * HID2P) + q);
#pragma unroll
    for (int i = 0; i < 4; i++) {
        float* dp = g_agg2 + (size_t)d[i] * HID2P + q * 4;
        asm volatile("red.global.add.v4.f32 [%0], {%1, %2, %3, %4};"
                     :: "l"(dp), "f"(v[i].x), "f"(v[i].y), "f"(v[i].z), "f"(v[i].w)
                     : "memory");
    }
}

// out = log_softmax(agg2)  (agg2 already holds agg + root + bias)
__global__ __launch_bounds__(128) void k_out(float* __restrict__ out) {
    int node = blockIdx.x * 128 + threadIdx.x;
    if (node >= N_NODES) return;

    const float* a = g_agg2 + (size_t)node * HID2P;
    float o[NCLS];
#pragma unroll
    for (int c = 0; c < NCLS; c++) o[c] = a[c];

    float m = o[0];
#pragma unroll
    for (int c = 1; c < NCLS; c++) m = fmaxf(m, o[c]);
    float sum = 0.f;
#pragma unroll
    for (int c = 0; c < NCLS; c++) sum += __expf(o[c] - m);
    float ls = m + logf(sum);
#pragma unroll
    for (int c = 0; c < NCLS; c++)
        out[(size_t)node * NCLS + c] = o[c] - ls;
}

// ---------------- launch ----------------
extern "C" void kernel_launch(void* const* d_in, const int* in_sizes, int n_in,
                              void* d_out, int out_size) {
    const float* x       = (const float*)d_in[0];
    const void*  ei      = d_in[1];
    const float* w_rel1  = (const float*)d_in[2];
    const float* b_rel1  = (const float*)d_in[3];
    const float* w_root1 = (const float*)d_in[4];
    const float* w_rel2  = (const float*)d_in[5];
    const float* b_rel2  = (const float*)d_in[6];
    const float* w_root2 = (const float*)d_in[7];
    float* out = (float*)d_out;

    static cudaStream_t s2 = nullptr;
    static cudaEvent_t evY, evR1, evS1, evR2;
    if (!s2) {
        cudaStreamCreateWithFlags(&s2, cudaStreamNonBlocking);
        cudaEventCreateWithFlags(&evY,  cudaEventDisableTiming);
        cudaEventCreateWithFlags(&evR1, cudaEventDisableTiming);
        cudaEventCreateWithFlags(&evS1, cudaEventDisableTiming);
        cudaEventCreateWithFlags(&evR2, cudaEventDisableTiming);
    }

    const int lin1Blocks = (N_NODES / 2 * 4 + 255) / 256;      // 391
    const int lin2Blocks = (N_NODES * 4 + 255) / 256;          // 782
    const int nodeBlocks = (N_NODES + 127) / 128;
    const int scat1Blocks = (EG * 4 + 255) / 256;
    const int scat2Blocks = ((int)(3u * EG) + 255) / 256;

    // Main: lin1y -> scat1 -> (wait lin1r) lin2h -> scat2 -> (wait lin2r) out
    // Side: (wait lin1y) lin1r [REDs race scat1] -> (wait scat1) lin2r [REDs race scat2]
    k_lin1y<<<lin1Blocks + 1, 256>>>(x, w_rel1, (const int*)ei);   // +1 detect
    cudaEventRecord(evY, 0);
    cudaStreamWaitEvent(s2, evY, 0);           // agg1 zeroed before root REDs
    k_lin1r<<<lin1Blocks, 256, 0, s2>>>(x, w_root1, b_rel1);
    cudaEventRecord(evR1, s2);

    k_scat1<<<scat1Blocks, 256>>>(ei);         // concurrent with lin1r
    cudaEventRecord(evS1, 0);

    cudaStreamWaitEvent(0, evR1, 0);           // agg1 fully assembled
    k_lin2h<<<lin2Blocks, 256>>>(w_rel2);

    cudaStreamWaitEvent(s2, evS1, 0);          // agg1 assembled for side too
    k_lin2r<<<lin2Blocks, 256, 0, s2>>>(w_root2, b_rel2);
    cudaEventRecord(evR2, s2);

    k_scat2<<<scat2Blocks, 256>>>(ei);         // REDs race lin2r's REDs

    cudaStreamWaitEvent(0, evR2, 0);           // agg2 fully assembled
    k_out<<<nodeBlocks, 128>>>(out);
}

// round 16
// speedup vs baseline: 1.1067x; 1.0257x over previous
#include <cuda_runtime.h>
#include <cuda_bf16.h>
#include <math.h>

#define N_NODES  50000
#define NHALF    (N_NODES / 2)
#define N_EDGES  1600000
#define EG       (N_EDGES / 4)
#define IN_CH    64
#define HID      16
#define NCLS     10
#define HID2P    12

// ---------------- device scratch ----------------
__device__ __align__(16) float g_y1  [N_NODES * HID];    // x @ w_rel1
__device__ __align__(16) float g_agg1[N_NODES * HID];    // 0 + RED(root1+b1) + RED(edges)
__device__ __align__(16) float g_y2  [N_NODES * HID2P];  // h @ w_rel2 (padded)
__device__ __align__(16) float g_agg2[N_NODES * HID2P];  // 0 + RED(root2+b2) + RED(edges)
__device__ int g_is64;                                   // edge dtype flag

// ---------------- kernels ----------------

// y1 = x @ w_rel1; zero agg1; detect edge dtype (last block).
// thread = pair*4 + part; pair = nodes {2p,2p+1}; part = column quarter.
__global__ __launch_bounds__(256) void k_lin1y(const float* __restrict__ x,
                                               const float* __restrict__ w_rel,
                                               const int* __restrict__ ei32) {
    if (blockIdx.x == gridDim.x - 1) {
        __shared__ int s_or;
        if (threadIdx.x == 0) s_or = 0;
        __syncthreads();
        int v = 0;
        for (int i = threadIdx.x; i < 1024; i += 256)
            v |= ei32[2 * i + 1];
        if (v) atomicOr(&s_or, 1);
        __syncthreads();
        if (threadIdx.x == 0) g_is64 = (s_or == 0) ? 1 : 0;
        return;
    }

    __shared__ float sw[IN_CH * HID];
    for (int i = threadIdx.x; i < IN_CH * HID; i += 256) sw[i] = w_rel[i];
    __syncthreads();

    int t = blockIdx.x * 256 + threadIdx.x;
    int pair = t >> 2;
    if (pair >= N_NODES / 2) return;
    int part = t & 3;
    int jbase = part * 4;
    int n0 = pair * 2, n1 = n0 + 1;

    // Zero agg1 for this pair: 8 float4s, 2 per part.
    {
        float4 z = make_float4(0.f, 0.f, 0.f, 0.f);
        float4* az = reinterpret_cast<float4*>(g_agg1 + (size_t)pair * 2 * HID);
        az[2 * part] = z;
        az[2 * part + 1] = z;
    }

    float a0[4] = {0.f, 0.f, 0.f, 0.f};
    float a1[4] = {0.f, 0.f, 0.f, 0.f};
    const float4* x0 = reinterpret_cast<const float4*>(x + (size_t)n0 * IN_CH);
    const float4* x1 = reinterpret_cast<const float4*>(x + (size_t)n1 * IN_CH);
#pragma unroll
    for (int k4 = 0; k4 < IN_CH / 4; k4++) {
        float4 v0 = __ldg(x0 + k4);
        float4 v1 = __ldg(x1 + k4);
        float s0[4] = {v0.x, v0.y, v0.z, v0.w};
        float s1[4] = {v1.x, v1.y, v1.z, v1.w};
#pragma unroll
        for (int u = 0; u < 4; u++) {
            const float* wr = sw + (k4 * 4 + u) * HID + jbase;
#pragma unroll
            for (int j = 0; j < 4; j++) {
                float wv = wr[j];
                a0[j] = fmaf(s0[u], wv, a0[j]);
                a1[j] = fmaf(s1[u], wv, a1[j]);
            }
        }
    }
    *reinterpret_cast<float4*>(g_y1 + (size_t)n0 * HID + jbase) =
        make_float4(a0[0], a0[1], a0[2], a0[3]);
    *reinterpret_cast<float4*>(g_y1 + (size_t)n1 * HID + jbase) =
        make_float4(a1[0], a1[1], a1[2], a1[3]);
}

// Root fold 1: RED-add (x@w_root1 + b1) into agg1. Commutes with scat1's
// REDs -> runs on side stream concurrently with scat1. Also zeroes agg2.
__global__ __launch_bounds__(256) void k_lin1r(const float* __restrict__ x,
                                               const float* __restrict__ w_root,
                                               const float* __restrict__ b1) {
    __shared__ float su[IN_CH * HID];
    __shared__ float sb[HID];
    for (int i = threadIdx.x; i < IN_CH * HID; i += 256) su[i] = w_root[i];
    if (threadIdx.x < HID) sb[threadIdx.x] = b1[threadIdx.x];
    __syncthreads();

    int t = blockIdx.x * 256 + threadIdx.x;
    int pair = t >> 2;
    if (pair >= N_NODES / 2) return;
    int part = t & 3;
    int jbase = part * 4;
    int n0 = pair * 2, n1 = n0 + 1;

    // Zero agg2 for this pair: 6 float4s over 4 parts.
    {
        float4 z = make_float4(0.f, 0.f, 0.f, 0.f);
        float4* az = reinterpret_cast<float4*>(g_agg2 + (size_t)pair * 2 * HID2P);
        if (part == 0)      { az[0] = z; az[1] = z; }
        else if (part == 1) { az[2] = z; az[3] = z; }
        else if (part == 2) { az[4] = z; }
        else                { az[5] = z; }
    }

    float a0[4], a1[4];
#pragma unroll
    for (int j = 0; j < 4; j++) { a0[j] = sb[jbase + j]; a1[j] = sb[jbase + j]; }
    const float4* x0 = reinterpret_cast<const float4*>(x + (size_t)n0 * IN_CH);
    const float4* x1 = reinterpret_cast<const float4*>(x + (size_t)n1 * IN_CH);
#pragma unroll
    for (int k4 = 0; k4 < IN_CH / 4; k4++) {
        float4 v0 = __ldg(x0 + k4);
        float4 v1 = __ldg(x1 + k4);
        float s0[4] = {v0.x, v0.y, v0.z, v0.w};
        float s1[4] = {v1.x, v1.y, v1.z, v1.w};
#pragma unroll
        for (int u = 0; u < 4; u++) {
            const float* wr = su + (k4 * 4 + u) * HID + jbase;
#pragma unroll
            for (int j = 0; j < 4; j++) {
                float wv = wr[j];
                a0[j] = fmaf(s0[u], wv, a0[j]);
                a1[j] = fmaf(s1[u], wv, a1[j]);
            }
        }
    }
    float* p0 = g_agg1 + (size_t)n0 * HID + jbase;
    float* p1 = g_agg1 + (size_t)n1 * HID + jbase;
    asm volatile("red.global.add.v4.f32 [%0], {%1, %2, %3, %4};"
                 :: "l"(p0), "f"(a0[0]), "f"(a0[1]), "f"(a0[2]), "f"(a0[3]) : "memory");
    asm volatile("red.global.add.v4.f32 [%0], {%1, %2, %3, %4};"
                 :: "l"(p1), "f"(a1[0]), "f"(a1[1]), "f"(a1[2]), "f"(a1[3]) : "memory");
}

// Layer-1 scatter, ILP=4: lanes q=0..3 share an edge group (coalesced rows).
__global__ __launch_bounds__(256) void k_scat1(const void* __restrict__ ei) {
    const bool is64 = (g_is64 != 0);
    int t = blockIdx.x * 256 + threadIdx.x;
    int eg = t >> 2;
    if (eg >= EG) return;
    int q = t & 3;
    int s[4], d[4];
    if (is64) {
        const long long* p = (const long long*)ei;
#pragma unroll
        for (int i = 0; i < 4; i++) {
            s[i] = (int)p[eg * 4 + i];
            d[i] = (int)p[N_EDGES + eg * 4 + i];
        }
    } else {
        const int* p = (const int*)ei;
        int4 sv = __ldg(reinterpret_cast<const int4*>(p) + eg);
        int4 dv = __ldg(reinterpret_cast<const int4*>(p + N_EDGES) + eg);
        s[0] = sv.x; s[1] = sv.y; s[2] = sv.z; s[3] = sv.w;
        d[0] = dv.x; d[1] = dv.y; d[2] = dv.z; d[3] = dv.w;
    }
    float4 v[4];
#pragma unroll
    for (int i = 0; i < 4; i++)
        v[i] = __ldg(reinterpret_cast<const float4*>(g_y1 + (size_t)s[i] * HID) + q);
#pragma unroll
    for (int i = 0; i < 4; i++) {
        float* dp = g_agg1 + (size_t)d[i] * HID + q * 4;
        asm volatile("red.global.add.v4.f32 [%0], {%1, %2, %3, %4};"
                     :: "l"(dp), "f"(v[i].x), "f"(v[i].y), "f"(v[i].z), "f"(v[i].w)
                     : "memory");
    }
}

// y2 = relu(agg1) @ w_rel2, ILP=2: thread = (pairIdx, sub) handles nodes
// pairIdx and pairIdx+NHALF. Two independent load->FMA chains fill issue
// slots; shfl_xor reduce over the 4-lane group; lane 0 stores both rows.
__global__ __launch_bounds__(256) void k_lin2h(const float* __restrict__ w_rel2) {
    __shared__ float sw[HID * NCLS];
    for (int i = threadIdx.x; i < HID * NCLS; i += 256) sw[i] = w_rel2[i];
    __syncthreads();

    int t = blockIdx.x * 256 + threadIdx.x;
    int pi = t >> 2;
    if (pi >= NHALF) return;
    int sub = t & 3;
    int nA = pi, nB = pi + NHALF;

    float4 aA = *(reinterpret_cast<const float4*>(g_agg1 + (size_t)nA * HID) + sub);
    float4 aB = *(reinterpret_cast<const float4*>(g_agg1 + (size_t)nB * HID) + sub);
    float hA[4] = {fmaxf(aA.x, 0.f), fmaxf(aA.y, 0.f), fmaxf(aA.z, 0.f), fmaxf(aA.w, 0.f)};
    float hB[4] = {fmaxf(aB.x, 0.f), fmaxf(aB.y, 0.f), fmaxf(aB.z, 0.f), fmaxf(aB.w, 0.f)};

    float yA[NCLS], yB[NCLS];
#pragma unroll
    for (int c = 0; c < NCLS; c++) { yA[c] = 0.f; yB[c] = 0.f; }
#pragma unroll
    for (int j = 0; j < 4; j++) {
        const float* wr = sw + (sub * 4 + j) * NCLS;
#pragma unroll
        for (int c = 0; c < NCLS; c++) {
            float wv = wr[c];
            yA[c] = fmaf(hA[j], wv, yA[c]);
            yB[c] = fmaf(hB[j], wv, yB[c]);
        }
    }
#pragma unroll
    for (int c = 0; c < NCLS; c++) {
        yA[c] += __shfl_xor_sync(0xffffffff, yA[c], 1);
        yA[c] += __shfl_xor_sync(0xffffffff, yA[c], 2);
        yB[c] += __shfl_xor_sync(0xffffffff, yB[c], 1);
        yB[c] += __shfl_xor_sync(0xffffffff, yB[c], 2);
    }
    if (sub == 0) {
        float4* y2A = reinterpret_cast<float4*>(g_y2 + (size_t)nA * HID2P);
        y2A[0] = make_float4(yA[0], yA[1], yA[2], yA[3]);
        y2A[1] = make_float4(yA[4], yA[5], yA[6], yA[7]);
        y2A[2] = make_float4(yA[8], yA[9], 0.f, 0.f);
        float4* y2B = reinterpret_cast<float4*>(g_y2 + (size_t)nB * HID2P);
        y2B[0] = make_float4(yB[0], yB[1], yB[2], yB[3]);
        y2B[1] = make_float4(yB[4], yB[5], yB[6], yB[7]);
        y2B[2] = make_float4(yB[8], yB[9], 0.f, 0.f);
    }
}

// Root fold 2, ILP=2: RED-add (relu(agg1)@w_root2 + b2) into agg2.
// Commutes with scat2's REDs -> side stream.
__global__ __launch_bounds__(256) void k_lin2r(const float* __restrict__ w_root2,
                                               const float* __restrict__ b2) {
    __shared__ float su[HID * NCLS];
    __shared__ float sb[NCLS];
    for (int i = threadIdx.x; i < HID * NCLS; i += 256) su[i] = w_root2[i];
    if (threadIdx.x < NCLS) sb[threadIdx.x] = b2[threadIdx.x];
    __syncthreads();

    int t = blockIdx.x * 256 + threadIdx.x;
    int pi = t >> 2;
    if (pi >= NHALF) return;
    int sub = t & 3;
    int nA = pi, nB = pi + NHALF;

    float4 aA = *(reinterpret_cast<const float4*>(g_agg1 + (size_t)nA * HID) + sub);
    float4 aB = *(reinterpret_cast<const float4*>(g_agg1 + (size_t)nB * HID) + sub);
    float hA[4] = {fmaxf(aA.x, 0.f), fmaxf(aA.y, 0.f), fmaxf(aA.z, 0.f), fmaxf(aA.w, 0.f)};
    float hB[4] = {fmaxf(aB.x, 0.f), fmaxf(aB.y, 0.f), fmaxf(aB.z, 0.f), fmaxf(aB.w, 0.f)};

    float yA[NCLS], yB[NCLS];
#pragma unroll
    for (int c = 0; c < NCLS; c++) {
        float init = (sub == 0) ? sb[c] : 0.f;   // bias folded in once
        yA[c] = init; yB[c] = init;
    }
#pragma unroll
    for (int j = 0; j < 4; j++) {
        const float* wr = su + (sub * 4 + j) * NCLS;
#pragma unroll
        for (int c = 0; c < NCLS; c++) {
            float wv = wr[c];
            yA[c] = fmaf(hA[j], wv, yA[c]);
            yB[c] = fmaf(hB[j], wv, yB[c]);
        }
    }
#pragma unroll
    for (int c = 0; c < NCLS; c++) {
        yA[c] += __shfl_xor_sync(0xffffffff, yA[c], 1);
        yA[c] += __shfl_xor_sync(0xffffffff, yA[c], 2);
        yB[c] += __shfl_xor_sync(0xffffffff, yB[c], 1);
        yB[c] += __shfl_xor_sync(0xffffffff, yB[c], 2);
    }
    if (sub == 0) {
        float* pA = g_agg2 + (size_t)nA * HID2P;
        asm volatile("red.global.add.v4.f32 [%0], {%1, %2, %3, %4};"
                     :: "l"(pA), "f"(yA[0]), "f"(yA[1]), "f"(yA[2]), "f"(yA[3]) : "memory");
        asm volatile("red.global.add.v4.f32 [%0], {%1, %2, %3, %4};"
                     :: "l"(pA + 4), "f"(yA[4]), "f"(yA[5]), "f"(yA[6]), "f"(yA[7]) : "memory");
        asm volatile("red.global.add.v4.f32 [%0], {%1, %2, %3, %4};"
                     :: "l"(pA + 8), "f"(yA[8]), "f"(yA[9]), "f"(0.f), "f"(0.f) : "memory");
        float* pB = g_agg2 + (size_t)nB * HID2P;
        asm volatile("red.global.add.v4.f32 [%0], {%1, %2, %3, %4};"
                     :: "l"(pB), "f"(yB[0]), "f"(yB[1]), "f"(yB[2]), "f"(yB[3]) : "memory");
        asm volatile("red.global.add.v4.f32 [%0], {%1, %2, %3, %4};"
                     :: "l"(pB + 4), "f"(yB[4]), "f"(yB[5]), "f"(yB[6]), "f"(yB[7]) : "memory");
        asm volatile("red.global.add.v4.f32 [%0], {%1, %2, %3, %4};"
                     :: "l"(pB + 8), "f"(yB[8]), "f"(yB[9]), "f"(0.f), "f"(0.f) : "memory");
    }
}

// Layer-2 scatter, ILP=4.
__global__ __launch_bounds__(256) void k_scat2(const void* __restrict__ ei) {
    const bool is64 = (g_is64 != 0);
    unsigned t = blockIdx.x * 256 + threadIdx.x;
    if (t >= 3u * EG) return;
    unsigned eg = (unsigned)(((unsigned long long)t * 0x55555556ULL) >> 32);  // t/3
    unsigned q = t - eg * 3u;
    int s[4], d[4];
    if (is64) {
        const long long* p = (const long long*)ei;
#pragma unroll
        for (int i = 0; i < 4; i++) {
            s[i] = (int)p[eg * 4 + i];
            d[i] = (int)p[N_EDGES + eg * 4 + i];
        }
    } else {
        const int* p = (const int*)ei;
        int4 sv = __ldg(reinterpret_cast<const int4*>(p) + eg);
        int4 dv = __ldg(reinterpret_cast<const int4*>(p + N_EDGES) + eg);
        s[0] = sv.x; s[1] = sv.y; s[2] = sv.z; s[3] = sv.w;
        d[0] = dv.x; d[1] = dv.y; d[2] = dv.z; d[3] = dv.w;
    }
    float4 v[4];
#pragma unroll
    for (int i = 0; i < 4; i++)
        v[i] = __ldg(reinterpret_cast<const float4*>(g_y2 + (size_t)s[i] * HID2P) + q);
#pragma unroll
    for (int i = 0; i < 4; i++) {
        float* dp = g_agg2 + (size_t)d[i] * HID2P + q * 4;
        asm volatile("red.global.add.v4.f32 [%0], {%1, %2, %3, %4};"
                     :: "l"(dp), "f"(v[i].x), "f"(v[i].y), "f"(v[i].z), "f"(v[i].w)
                     : "memory");
    }
}

// out = log_softmax(agg2)  (agg2 already holds agg + root + bias)
__global__ __launch_bounds__(128) void k_out(float* __restrict__ out) {
    int node = blockIdx.x * 128 + threadIdx.x;
    if (node >= N_NODES) return;

    const float* a = g_agg2 + (size_t)node * HID2P;
    float o[NCLS];
#pragma unroll
    for (int c = 0; c < NCLS; c++) o[c] = a[c];

    float m = o[0];
#pragma unroll
    for (int c = 1; c < NCLS; c++) m = fmaxf(m, o[c]);
    float sum = 0.f;
#pragma unroll
    for (int c = 0; c < NCLS; c++) sum += __expf(o[c] - m);
    float ls = m + logf(sum);
#pragma unroll
    for (int c = 0; c < NCLS; c++)
        out[(size_t)node * NCLS + c] = o[c] - ls;
}

// ---------------- launch ----------------
extern "C" void kernel_launch(void* const* d_in, const int* in_sizes, int n_in,
                              void* d_out, int out_size) {
    const float* x       = (const float*)d_in[0];
    const void*  ei      = d_in[1];
    const float* w_rel1  = (const float*)d_in[2];
    const float* b_rel1  = (const float*)d_in[3];
    const float* w_root1 = (const float*)d_in[4];
    const float* w_rel2  = (const float*)d_in[5];
    const float* b_rel2  = (const float*)d_in[6];
    const float* w_root2 = (const float*)d_in[7];
    float* out = (float*)d_out;

    static cudaStream_t s2 = nullptr;
    static cudaEvent_t evY, evR1, evS1, evR2;
    if (!s2) {
        cudaStreamCreateWithFlags(&s2, cudaStreamNonBlocking);
        cudaEventCreateWithFlags(&evY,  cudaEventDisableTiming);
        cudaEventCreateWithFlags(&evR1, cudaEventDisableTiming);
        cudaEventCreateWithFlags(&evS1, cudaEventDisableTiming);
        cudaEventCreateWithFlags(&evR2, cudaEventDisableTiming);
    }

    const int lin1Blocks = (N_NODES / 2 * 4 + 255) / 256;      // 391
    const int lin2Blocks = (NHALF * 4 + 255) / 256;            // 391
    const int nodeBlocks = (N_NODES + 127) / 128;
    const int scat1Blocks = (EG * 4 + 255) / 256;
    const int scat2Blocks = ((int)(3u * EG) + 255) / 256;

    // Main: lin1y -> scat1 -> (wait lin1r) lin2h -> scat2 -> (wait lin2r) out
    // Side: (wait lin1y) lin1r [REDs race scat1] -> (wait scat1) lin2r [REDs race scat2]
    k_lin1y<<<lin1Blocks + 1, 256>>>(x, w_rel1, (const int*)ei);   // +1 detect
    cudaEventRecord(evY, 0);
    cudaStreamWaitEvent(s2, evY, 0);           // agg1 zeroed before root REDs
    k_lin1r<<<lin1Blocks, 256, 0, s2>>>(x, w_root1, b_rel1);
    cudaEventRecord(evR1, s2);

    k_scat1<<<scat1Blocks, 256>>>(ei);         // concurrent with lin1r
    cudaEventRecord(evS1, 0);

    cudaStreamWaitEvent(0, evR1, 0);           // agg1 fully assembled
    k_lin2h<<<lin2Blocks, 256>>>(w_rel2);

    cudaStreamWaitEvent(s2, evS1, 0);          // agg1 assembled for side too
    k_lin2r<<<lin2Blocks, 256, 0, s2>>>(w_root2, b_rel2);
    cudaEventRecord(evR2, s2);

    k_scat2<<<scat2Blocks, 256>>>(ei);         // REDs race lin2r's REDs

    cudaStreamWaitEvent(0, evR2, 0);           // agg2 fully assembled
    k_out<<<nodeBlocks, 128>>>(out);
}